// round 10
// baseline (speedup 1.0000x reference)
#include <cuda_runtime.h>
#include <cuda_bf16.h>
#include <cstdint>

#define NN 50000
#define EE 800000
#define FN 128
#define HA 64
#define NH 8

// ---------------- scratch ----------------
__device__ float g_prop_src[NN * FN];
__device__ float g_prop_dst[NN * FN];
__device__ float g_hs[NN * HA];
__device__ float g_hd[NN * HA];
__device__ float g_a_src[NN * NH];
__device__ float g_a_dst[NN * NH];
__device__ float g_att[EE * NH];     // dst-sorted order
__device__ int   g_deg[NN];          // zero at module load; re-zeroed by softmax_agg
__device__ int   g_off[NN];
__device__ int   g_cur[NN];
__device__ int   g_pos[EE];          // edge -> sorted slot
__device__ int   g_srcs[EE];         // src id in sorted order

// ================= K1: fused node GEMM (bf16 mma m16n8k16, 2-term split) ==
// C[50000 x 384] = feat @ [wps | wpd | was0|wad0],  K = 128
// grid = (782, 3); block = 256 (8 warps: 4 m-warps x 2 n-warps)
// block tile: M=64, N=128, K chunked by 32 (16 bf16x2 pairs).
// split: x = hi + lo (bf16 each, 16 mantissa bits total); products
// hi*hi + hi*lo + lo*hi; omitted lo*lo ~ 2^-18 relative.
#define MT 64
#define CH 32
#define AS2 20    // A smem row stride in u32 pairs (16 pairs + 4 pad)
#define BS2 136   // B smem row stride in u32 pairs (128 cols + 8 pad)

__device__ __forceinline__ void split_bf16x2(float x, float y,
                                             uint32_t& hi, uint32_t& lo) {
    // pack (x -> low half, y -> high half): element order = ascending k
    __nv_bfloat16 hx = __float2bfloat16(x);
    __nv_bfloat16 hy = __float2bfloat16(y);
    float rx = x - __bfloat162float(hx);
    float ry = y - __bfloat162float(hy);
    __nv_bfloat16 lx = __float2bfloat16(rx);
    __nv_bfloat16 ly = __float2bfloat16(ry);
    hi = ((uint32_t)__bfloat16_as_ushort(hy) << 16) | __bfloat16_as_ushort(hx);
    lo = ((uint32_t)__bfloat16_as_ushort(ly) << 16) | __bfloat16_as_ushort(lx);
}

__device__ __forceinline__ void mma_bf16(float* c, const uint32_t* a,
                                         uint32_t b0, uint32_t b1) {
    asm volatile(
        "mma.sync.aligned.m16n8k16.row.col.f32.bf16.bf16.f32 "
        "{%0,%1,%2,%3}, {%4,%5,%6,%7}, {%8,%9}, {%0,%1,%2,%3};"
        : "+f"(c[0]), "+f"(c[1]), "+f"(c[2]), "+f"(c[3])
        : "r"(a[0]), "r"(a[1]), "r"(a[2]), "r"(a[3]), "r"(b0), "r"(b1));
}

__global__ void __launch_bounds__(256) node_gemm_kernel(
    const float* __restrict__ feat,
    const float* __restrict__ wps, const float* __restrict__ bps,
    const float* __restrict__ wpd, const float* __restrict__ bpd,
    const float* __restrict__ was0, const float* __restrict__ wad0)
{
    __shared__ uint32_t sAh[MT * AS2];      // 64 rows x 16 pairs (+pad)
    __shared__ uint32_t sAl[MT * AS2];
    __shared__ uint32_t sBh[16 * BS2];      // 16 k-pairs x 128 cols (+pad)
    __shared__ uint32_t sBl[16 * BS2];

    const int tid = threadIdx.x;
    const int m0 = blockIdx.x * MT;
    const int nb = blockIdx.y;               // 0: wps, 1: wpd, 2: [was0|wad0]

    const int wid = tid >> 5;
    const int lane = tid & 31;
    const int warp_m = wid & 3;              // m offset *16
    const int warp_n = wid >> 2;             // n offset *64
    const int gid = lane >> 2;               // 0..7
    const int tig = lane & 3;                // 0..3
    const int m_w = warp_m * 16;
    const int n_w = warp_n * 64;

    float acc[8][4];
    #pragma unroll
    for (int j = 0; j < 8; j++)
        #pragma unroll
        for (int i = 0; i < 4; i++) acc[j][i] = 0.f;

    for (int kc = 0; kc < FN; kc += CH) {
        // ---- stage A: feat[m0..m0+63][kc..kc+31] -> bf16 hi/lo pairs
        #pragma unroll
        for (int p = 0; p < 2; p++) {
            int idx = tid + p * 256;          // 0..511 (64 rows x 8 float4)
            int row = idx >> 3;
            int q = (idx & 7) * 4;            // k offset within chunk
            int node = m0 + row;
            float4 v = make_float4(0.f, 0.f, 0.f, 0.f);
            if (node < NN)
                v = *reinterpret_cast<const float4*>(&feat[node * FN + kc + q]);
            uint32_t h0, l0, h1, l1;
            split_bf16x2(v.x, v.y, h0, l0);
            split_bf16x2(v.z, v.w, h1, l1);
            int base = row * AS2 + (q >> 1);
            sAh[base] = h0; sAh[base + 1] = h1;
            sAl[base] = l0; sAl[base + 1] = l1;
        }
        // ---- stage B: W[kc..kc+31][0..127] -> [kpair][col] bf16 pairs
        #pragma unroll
        for (int p = 0; p < 8; p++) {
            int idx = tid + p * 256;          // 0..2047 (16 kpairs x 128 cols)
            int c = idx & 127;
            int kp = idx >> 7;
            int k0 = kc + 2 * kp;
            float x, y;
            if (nb == 0) {
                x = wps[k0 * FN + c];
                y = wps[(k0 + 1) * FN + c];
            } else if (nb == 1) {
                x = wpd[k0 * FN + c];
                y = wpd[(k0 + 1) * FN + c];
            } else if (c < 64) {
                x = was0[k0 * HA + c];
                y = was0[(k0 + 1) * HA + c];
            } else {
                x = wad0[k0 * HA + c - 64];
                y = wad0[(k0 + 1) * HA + c - 64];
            }
            uint32_t h, l;
            split_bf16x2(x, y, h, l);
            sBh[kp * BS2 + c] = h;
            sBl[kp * BS2 + c] = l;
        }
        __syncthreads();

        // ---- mma over 2 k-steps of 16 (8 pairs each)
        #pragma unroll
        for (int ks = 0; ks < 2; ks++) {
            int kp0 = ks * 8;
            int abase = (m_w + gid) * AS2 + kp0 + tig;
            uint32_t ah[4], al[4];
            ah[0] = sAh[abase];               al[0] = sAl[abase];
            ah[1] = sAh[abase + 8 * AS2];     al[1] = sAl[abase + 8 * AS2];
            ah[2] = sAh[abase + 4];           al[2] = sAl[abase + 4];
            ah[3] = sAh[abase + 8 * AS2 + 4]; al[3] = sAl[abase + 8 * AS2 + 4];
            #pragma unroll
            for (int j = 0; j < 8; j++) {
                int col = n_w + j * 8 + gid;
                int b0i = (kp0 + tig) * BS2 + col;
                int b1i = b0i + 4 * BS2;
                uint32_t bh0 = sBh[b0i], bh1 = sBh[b1i];
                uint32_t bl0 = sBl[b0i], bl1 = sBl[b1i];
                mma_bf16(acc[j], ah, bh0, bh1);   // hi*hi
                mma_bf16(acc[j], ah, bl0, bl1);   // hi*lo
                mma_bf16(acc[j], al, bh0, bh1);   // lo*hi
            }
        }
        __syncthreads();
    }

    // ---- epilogue (C layout: row gid/gid+8, cols 2*tig, 2*tig+1)
    #pragma unroll
    for (int half = 0; half < 2; half++) {
        int node = m0 + m_w + gid + half * 8;
        if (node >= NN) continue;
        #pragma unroll
        for (int j = 0; j < 8; j++) {
            int col = n_w + j * 8 + tig * 2;
            float v0 = acc[j][half * 2 + 0];
            float v1 = acc[j][half * 2 + 1];
            if (nb == 0) {
                g_prop_src[node * FN + col]     = v0 + bps[col];
                g_prop_src[node * FN + col + 1] = v1 + bps[col + 1];
            } else if (nb == 1) {
                g_prop_dst[node * FN + col]     = v0 + bpd[col];
                g_prop_dst[node * FN + col + 1] = v1 + bpd[col + 1];
            } else if (warp_n == 0) {
                g_hs[node * HA + col]     = fmaxf(v0, 0.f);
                g_hs[node * HA + col + 1] = fmaxf(v1, 0.f);
            } else {
                g_hd[node * HA + col - 64] = fmaxf(v0, 0.f);
                g_hd[node * HA + col - 63] = fmaxf(v1, 0.f);
            }
        }
    }
}

// ================= K2: attention second layer ============================
#define NB2 8
__global__ void __launch_bounds__(128) att_layer2_kernel(
    const float* __restrict__ was1, const float* __restrict__ wad1)
{
    __shared__ __align__(16) float hs[NB2][HA];
    __shared__ __align__(16) float hd[NB2][HA];
    int t = threadIdx.x;
    int n0 = blockIdx.x * NB2;

    #pragma unroll
    for (int p = 0; p < 4; p++) {
        int idx = t + p * 128;               // 0..511
        int j = idx >> 6, c = idx & 63;
        hs[j][c] = g_hs[(n0 + j) * HA + c];
        hd[j][c] = g_hd[(n0 + j) * HA + c];
    }
    __syncthreads();

    int j = t >> 4, r = t & 15;
    if (r < NH) {
        float a = 0.f;
        #pragma unroll 8
        for (int k = 0; k < HA; k++) a += hs[j][k] * was1[k * NH + r];
        g_a_src[(n0 + j) * NH + r] = a;
    } else {
        int h = r - NH;
        float a = 0.f;
        #pragma unroll 8
        for (int k = 0; k < HA; k++) a += hd[j][k] * wad1[k * NH + h];
        g_a_dst[(n0 + j) * NH + h] = a;
    }
}

// ================= CSR build =============================================
// g_deg starts zero (module load) and is re-zeroed by softmax_agg each run.
__global__ void count_deg_kernel(const int* __restrict__ dst)
{
    int e = blockIdx.x * 256 + threadIdx.x;
    if (e < EE) atomicAdd(&g_deg[dst[e]], 1);
}

// thread-coarsened single-block scan: 1024 thr x 49 elems
__global__ void __launch_bounds__(1024) scan_deg_kernel()
{
    __shared__ int wsums[32];
    const int C = 49;
    int t = threadIdx.x;
    int lane = t & 31, wid = t >> 5;
    int begin = t * C;

    int s = 0;
    for (int i = 0; i < C; i++) {
        int idx = begin + i;
        if (idx < NN) s += g_deg[idx];
    }
    int incl = s;
    #pragma unroll
    for (int o = 1; o < 32; o <<= 1) {
        int v = __shfl_up_sync(0xffffffff, incl, o);
        if (lane >= o) incl += v;
    }
    if (lane == 31) wsums[wid] = incl;
    __syncthreads();
    if (wid == 0) {
        int w = wsums[lane];
        int wi = w;
        #pragma unroll
        for (int o = 1; o < 32; o <<= 1) {
            int v = __shfl_up_sync(0xffffffff, wi, o);
            if (lane >= o) wi += v;
        }
        wsums[lane] = wi - w;                // exclusive warp base
    }
    __syncthreads();

    int run = wsums[wid] + incl - s;         // exclusive prefix for this thread
    for (int i = 0; i < C; i++) {
        int idx = begin + i;
        if (idx < NN) {
            g_off[idx] = run;
            g_cur[idx] = run;
            run += g_deg[idx];
        }
    }
}

__global__ void scatter_edges_kernel(const int* __restrict__ src,
                                     const int* __restrict__ dst)
{
    int e = blockIdx.x * 256 + threadIdx.x;
    if (e < EE) {
        int p = atomicAdd(&g_cur[dst[e]], 1);
        g_pos[e] = p;
        g_srcs[p] = src[e];
    }
}

// ================= K5: edge MLP + attention logits (write sorted) =========
#define FEG 8
__global__ void __launch_bounds__(256) edge_att_kernel(
    const float* __restrict__ fe_g,
    const int* __restrict__ src, const int* __restrict__ dst,
    const float* __restrict__ we0, const float* __restrict__ we1)
{
    __shared__ __align__(16) float we0t[HA * FEG];  // [c][k]
    __shared__ __align__(16) float we1s[HA * NH];   // [c][h]

    int t = threadIdx.x;
    #pragma unroll
    for (int i = t; i < HA * FEG; i += 256) {
        int c = i >> 3, k = i & 7;
        we0t[i] = we0[k * HA + c];
        we1s[i] = we1[i];
    }
    __syncthreads();

    int e = blockIdx.x * 256 + t;
    if (e >= EE) return;

    float4 f0 = reinterpret_cast<const float4*>(fe_g)[e * 2];
    float4 f1 = reinterpret_cast<const float4*>(fe_g)[e * 2 + 1];

    float a[NH];
    #pragma unroll
    for (int h = 0; h < NH; h++) a[h] = 0.f;

    #pragma unroll 4
    for (int c = 0; c < HA; c++) {
        float4 wa = reinterpret_cast<const float4*>(we0t + c * 8)[0];
        float4 wb = reinterpret_cast<const float4*>(we0t + c * 8)[1];
        float hsum = f0.x*wa.x + f0.y*wa.y + f0.z*wa.z + f0.w*wa.w
                   + f1.x*wb.x + f1.y*wb.y + f1.z*wb.z + f1.w*wb.w;
        hsum = fmaxf(hsum, 0.f);
        float4 va = reinterpret_cast<const float4*>(we1s + c * 8)[0];
        float4 vb = reinterpret_cast<const float4*>(we1s + c * 8)[1];
        a[0] += hsum * va.x; a[1] += hsum * va.y;
        a[2] += hsum * va.z; a[3] += hsum * va.w;
        a[4] += hsum * vb.x; a[5] += hsum * vb.y;
        a[6] += hsum * vb.z; a[7] += hsum * vb.w;
    }

    int s = src[e], d = dst[e];
    float4 s0 = reinterpret_cast<const float4*>(g_a_src)[s * 2];
    float4 s1 = reinterpret_cast<const float4*>(g_a_src)[s * 2 + 1];
    float4 d0 = reinterpret_cast<const float4*>(g_a_dst)[d * 2];
    float4 d1 = reinterpret_cast<const float4*>(g_a_dst)[d * 2 + 1];

    float4 o0, o1;
    o0.x = fmaxf(a[0] + s0.x + d0.x, 0.f);
    o0.y = fmaxf(a[1] + s0.y + d0.y, 0.f);
    o0.z = fmaxf(a[2] + s0.z + d0.z, 0.f);
    o0.w = fmaxf(a[3] + s0.w + d0.w, 0.f);
    o1.x = fmaxf(a[4] + s1.x + d1.x, 0.f);
    o1.y = fmaxf(a[5] + s1.y + d1.y, 0.f);
    o1.z = fmaxf(a[6] + s1.z + d1.z, 0.f);
    o1.w = fmaxf(a[7] + s1.w + d1.w, 0.f);

    int p = g_pos[e];
    reinterpret_cast<float4*>(g_att)[p * 2]     = o0;
    reinterpret_cast<float4*>(g_att)[p * 2 + 1] = o1;
}

// ================= K6: single-pass softmax + aggregate + residual =========
// one warp per dst node; lane l owns cols 4l..4l+3 (head l>>2)
// also re-zeroes g_deg[n] for the next graph replay (count_deg precondition)
__global__ void __launch_bounds__(256) softmax_agg_kernel(float* __restrict__ out)
{
    int warp = threadIdx.x >> 5;
    int l    = threadIdx.x & 31;
    int n = blockIdx.x * 8 + warp;
    if (n >= NN) return;

    int start = g_off[n];
    int cnt   = g_deg[n];
    if (l == 0) g_deg[n] = 0;     // reset for next replay
    int h     = l >> 2;

    float4 acc = make_float4(0.f, 0.f, 0.f, 0.f);
    float den = 0.f;
    for (int j = 0; j < cnt; j++) {
        int p = start + j;
        float ex = __expf(__ldg(&g_att[p * NH + h]));
        den += ex;
        int s = g_srcs[p];
        float4 v = reinterpret_cast<const float4*>(g_prop_src)[s * 32 + l];
        acc.x += ex * v.x;
        acc.y += ex * v.y;
        acc.z += ex * v.z;
        acc.w += ex * v.w;
    }

    float inv = 1.f / fmaxf(den, 1e-16f);
    float4 pd = reinterpret_cast<const float4*>(g_prop_dst)[n * 32 + l];
    float4 o;
    o.x = acc.x * inv + pd.x;
    o.y = acc.y * inv + pd.y;
    o.z = acc.z * inv + pd.z;
    o.w = acc.w * inv + pd.w;
    reinterpret_cast<float4*>(out)[n * 32 + l] = o;
}

// ================= launch ================================================
extern "C" void kernel_launch(void* const* d_in, const int* in_sizes, int n_in,
                              void* d_out, int out_size)
{
    const float* feat      = (const float*)d_in[0];
    const float* feat_edge = (const float*)d_in[1];
    const int*   src       = (const int*)  d_in[2];
    const int*   dst       = (const int*)  d_in[3];
    const float* was0      = (const float*)d_in[4];
    const float* was1      = (const float*)d_in[5];
    const float* wad0      = (const float*)d_in[6];
    const float* wad1      = (const float*)d_in[7];
    const float* we0       = (const float*)d_in[8];
    const float* we1       = (const float*)d_in[9];
    const float* wps       = (const float*)d_in[10];
    const float* bps       = (const float*)d_in[11];
    const float* wpd       = (const float*)d_in[12];
    const float* bpd       = (const float*)d_in[13];
    float* out = (float*)d_out;

    // CSR build (g_deg zeroed by previous softmax_agg / module load)
    count_deg_kernel<<<(EE + 255) / 256, 256>>>(dst);
    scan_deg_kernel<<<1, 1024>>>();
    scatter_edges_kernel<<<(EE + 255) / 256, 256>>>(src, dst);

    // fused node GEMM (launch #4 — lands in the ncu capture slot)
    node_gemm_kernel<<<dim3((NN + MT - 1) / MT, 3), 256>>>(
        feat, wps, bps, wpd, bpd, was0, wad0);
    att_layer2_kernel<<<NN / NB2, 128>>>(was1, wad1);

    // edge MLP + logits (written in CSR order)
    edge_att_kernel<<<(EE + 255) / 256, 256>>>(feat_edge, src, dst, we0, we1);

    // single-pass softmax + aggregation + residual (+ g_deg reset)
    softmax_agg_kernel<<<(NN + 7) / 8, 256>>>(out);
}

// round 13
// speedup vs baseline: 1.1000x; 1.1000x over previous
#include <cuda_runtime.h>
#include <cuda_bf16.h>
#include <cstdint>

#define NN 50000
#define EE 800000
#define FN 128
#define HA 64
#define NH 8

// ---------------- scratch ----------------
__device__ float g_prop_src[NN * FN];
__device__ float g_prop_dst[NN * FN];
__device__ float g_hs[NN * HA];
__device__ float g_hd[NN * HA];
__device__ float g_a_src[NN * NH];
__device__ float g_a_dst[NN * NH];
__device__ float g_att[EE * NH];     // dst-sorted order
__device__ int   g_deg[NN];          // zero at module load; re-zeroed by softmax_agg
__device__ int   g_off[NN];
__device__ int   g_cur[NN];
__device__ int   g_pos[EE];          // edge -> sorted slot
__device__ int   g_srcs[EE];         // src id in sorted order

// pre-split bf16 hi/lo pairs (u32 = bf16x2, low half = even k)
__device__ uint32_t g_Ah[NN * 64];   // feat  [node][kpair]
__device__ uint32_t g_Al[NN * 64];
__device__ uint32_t g_Bh[6 * 64 * 64]; // [ypanel][kpair][col]  (64 cols per panel)
__device__ uint32_t g_Bl[6 * 64 * 64];

__device__ __forceinline__ void split_bf16x2(float x, float y,
                                             uint32_t& hi, uint32_t& lo) {
    __nv_bfloat16 hx = __float2bfloat16(x);
    __nv_bfloat16 hy = __float2bfloat16(y);
    float rx = x - __bfloat162float(hx);
    float ry = y - __bfloat162float(hy);
    __nv_bfloat16 lx = __float2bfloat16(rx);
    __nv_bfloat16 ly = __float2bfloat16(ry);
    hi = ((uint32_t)__bfloat16_as_ushort(hy) << 16) | __bfloat16_as_ushort(hx);
    lo = ((uint32_t)__bfloat16_as_ushort(ly) << 16) | __bfloat16_as_ushort(lx);
}

// ================= P1: split feat -> bf16 hi/lo pairs ====================
__global__ void __launch_bounds__(256) split_feat_kernel(const float* __restrict__ feat)
{
    int idx = blockIdx.x * 256 + threadIdx.x;     // 0 .. NN*64-1
    float2 v = reinterpret_cast<const float2*>(feat)[idx];
    uint32_t h, l;
    split_bf16x2(v.x, v.y, h, l);
    g_Ah[idx] = h;
    g_Al[idx] = l;
}

// ================= P2: split weights -> panels ===========================
// panel y: 0,1 = wps cols [0:64),[64:128); 2,3 = wpd; 4 = was0; 5 = wad0
__global__ void __launch_bounds__(256) split_w_kernel(
    const float* __restrict__ wps, const float* __restrict__ wpd,
    const float* __restrict__ was0, const float* __restrict__ wad0)
{
    int idx = blockIdx.x * 256 + threadIdx.x;     // 0 .. 6*64*64-1
    int y  = idx >> 12;
    int kp = (idx >> 6) & 63;
    int c  = idx & 63;
    int k0 = kp * 2;
    float x, z;
    if (y < 2) {
        int col = (y & 1) * 64 + c;
        x = wps[k0 * FN + col]; z = wps[(k0 + 1) * FN + col];
    } else if (y < 4) {
        int col = (y & 1) * 64 + c;
        x = wpd[k0 * FN + col]; z = wpd[(k0 + 1) * FN + col];
    } else if (y == 4) {
        x = was0[k0 * HA + c]; z = was0[(k0 + 1) * HA + c];
    } else {
        x = wad0[k0 * HA + c]; z = wad0[(k0 + 1) * HA + c];
    }
    uint32_t h, l;
    split_bf16x2(x, z, h, l);
    g_Bh[idx] = h;
    g_Bl[idx] = l;
}

// ================= K1: node GEMM (bf16 m16n8k16, pre-split operands) =====
// C[50000 x 384] = feat @ [wps | wpd | was0|wad0], panels of 64 cols.
// grid = (782, 6); block = 256 (8 warps: 4 m x 2 n), warp tile m16 x n32.
// products hi*hi + hi*lo + lo*hi (lo*lo ~2^-18 omitted).
#define MT 64
#define ASP 20   // A smem row stride (16 kpairs + 4 pad u32)
#define BSP 72   // B smem row stride (64 cols + 8 pad u32)

__device__ __forceinline__ void mma_bf16(float* c, const uint32_t* a,
                                         uint32_t b0, uint32_t b1) {
    asm volatile(
        "mma.sync.aligned.m16n8k16.row.col.f32.bf16.bf16.f32 "
        "{%0,%1,%2,%3}, {%4,%5,%6,%7}, {%8,%9}, {%0,%1,%2,%3};"
        : "+f"(c[0]), "+f"(c[1]), "+f"(c[2]), "+f"(c[3])
        : "r"(a[0]), "r"(a[1]), "r"(a[2]), "r"(a[3]), "r"(b0), "r"(b1));
}

__global__ void __launch_bounds__(256, 3) node_gemm_kernel(
    const float* __restrict__ bps, const float* __restrict__ bpd)
{
    __shared__ uint32_t sAh[MT * ASP];   // 64 x (16+4)
    __shared__ uint32_t sAl[MT * ASP];
    __shared__ uint32_t sBh[16 * BSP];   // 16 kpairs x (64+8)
    __shared__ uint32_t sBl[16 * BSP];

    const int tid = threadIdx.x;
    const int m0 = blockIdx.x * MT;
    const int yp = blockIdx.y;

    const int wid = tid >> 5;
    const int lane = tid & 31;
    const int warp_m = wid & 3;
    const int warp_n = wid >> 2;         // 0/1
    const int gid = lane >> 2;           // 0..7
    const int tig = lane & 3;            // 0..3
    const int m_w = warp_m * 16;
    const int n_w = warp_n * 32;

    // staging indices
    const int arow = tid >> 2;           // 0..63
    const int agrp = tid & 3;            // 0..3  (4 uint4 per A row)
    const int anode = m0 + arow;
    const int brow = tid >> 4;           // 0..15 (kpair within chunk)
    const int bgrp = tid & 15;           // 0..15 (16 uint4 per B row)

    float acc[4][4];
    #pragma unroll
    for (int j = 0; j < 4; j++)
        #pragma unroll
        for (int i = 0; i < 4; i++) acc[j][i] = 0.f;

    #pragma unroll
    for (int ck = 0; ck < 4; ck++) {
        int kc2 = ck * 16;               // kpair offset of chunk

        // ---- stage A (pure copy): 64 rows x 16 u32 hi + lo
        {
            uint4 vh = make_uint4(0u, 0u, 0u, 0u);
            uint4 vl = make_uint4(0u, 0u, 0u, 0u);
            if (anode < NN) {
                int gi = anode * 16 + (kc2 >> 2) + agrp;   // uint4 index
                vh = reinterpret_cast<const uint4*>(g_Ah)[gi];
                vl = reinterpret_cast<const uint4*>(g_Al)[gi];
            }
            reinterpret_cast<uint4*>(sAh)[arow * 5 + agrp] = vh;  // 20 u32 = 5 uint4
            reinterpret_cast<uint4*>(sAl)[arow * 5 + agrp] = vl;
        }
        // ---- stage B (pure copy): 16 kpairs x 64 u32 hi + lo
        {
            int gi = yp * 1024 + (kc2 + brow) * 16 + bgrp;        // uint4 index
            uint4 vh = reinterpret_cast<const uint4*>(g_Bh)[gi];
            uint4 vl = reinterpret_cast<const uint4*>(g_Bl)[gi];
            reinterpret_cast<uint4*>(sBh)[brow * 18 + bgrp] = vh; // 72 u32 = 18 uint4
            reinterpret_cast<uint4*>(sBl)[brow * 18 + bgrp] = vl;
        }
        __syncthreads();

        // ---- mma: 2 k-steps of 16
        #pragma unroll
        for (int ks = 0; ks < 2; ks++) {
            int kp0 = ks * 8;
            int abase = (m_w + gid) * ASP + kp0 + tig;
            uint32_t ah[4], al[4];
            ah[0] = sAh[abase];               al[0] = sAl[abase];
            ah[1] = sAh[abase + 8 * ASP];     al[1] = sAl[abase + 8 * ASP];
            ah[2] = sAh[abase + 4];           al[2] = sAl[abase + 4];
            ah[3] = sAh[abase + 8 * ASP + 4]; al[3] = sAl[abase + 8 * ASP + 4];
            #pragma unroll
            for (int j = 0; j < 4; j++) {
                int col = n_w + j * 8 + gid;
                int b0i = (kp0 + tig) * BSP + col;
                int b1i = b0i + 4 * BSP;
                uint32_t bh0 = sBh[b0i], bh1 = sBh[b1i];
                uint32_t bl0 = sBl[b0i], bl1 = sBl[b1i];
                mma_bf16(acc[j], ah, bh0, bh1);   // hi*hi
                mma_bf16(acc[j], ah, bl0, bl1);   // hi*lo
                mma_bf16(acc[j], al, bh0, bh1);   // lo*hi
            }
        }
        __syncthreads();
    }

    // ---- epilogue: C row gid/gid+8, cols 2*tig/2*tig+1 within n8 block
    #pragma unroll
    for (int half = 0; half < 2; half++) {
        int node = m0 + m_w + gid + half * 8;
        if (node >= NN) continue;
        #pragma unroll
        for (int j = 0; j < 4; j++) {
            int cl = n_w + j * 8 + tig * 2;      // 0..63 within panel
            float v0 = acc[j][half * 2 + 0];
            float v1 = acc[j][half * 2 + 1];
            if (yp < 2) {
                int col = (yp & 1) * 64 + cl;
                g_prop_src[node * FN + col]     = v0 + bps[col];
                g_prop_src[node * FN + col + 1] = v1 + bps[col + 1];
            } else if (yp < 4) {
                int col = (yp & 1) * 64 + cl;
                g_prop_dst[node * FN + col]     = v0 + bpd[col];
                g_prop_dst[node * FN + col + 1] = v1 + bpd[col + 1];
            } else if (yp == 4) {
                g_hs[node * HA + cl]     = fmaxf(v0, 0.f);
                g_hs[node * HA + cl + 1] = fmaxf(v1, 0.f);
            } else {
                g_hd[node * HA + cl]     = fmaxf(v0, 0.f);
                g_hd[node * HA + cl + 1] = fmaxf(v1, 0.f);
            }
        }
    }
}

// ================= K2: attention second layer ============================
#define NB2 8
__global__ void __launch_bounds__(128) att_layer2_kernel(
    const float* __restrict__ was1, const float* __restrict__ wad1)
{
    __shared__ __align__(16) float hs[NB2][HA];
    __shared__ __align__(16) float hd[NB2][HA];
    int t = threadIdx.x;
    int n0 = blockIdx.x * NB2;

    #pragma unroll
    for (int p = 0; p < 4; p++) {
        int idx = t + p * 128;
        int j = idx >> 6, c = idx & 63;
        hs[j][c] = g_hs[(n0 + j) * HA + c];
        hd[j][c] = g_hd[(n0 + j) * HA + c];
    }
    __syncthreads();

    int j = t >> 4, r = t & 15;
    if (r < NH) {
        float a = 0.f;
        #pragma unroll 8
        for (int k = 0; k < HA; k++) a += hs[j][k] * was1[k * NH + r];
        g_a_src[(n0 + j) * NH + r] = a;
    } else {
        int h = r - NH;
        float a = 0.f;
        #pragma unroll 8
        for (int k = 0; k < HA; k++) a += hd[j][k] * wad1[k * NH + h];
        g_a_dst[(n0 + j) * NH + h] = a;
    }
}

// ================= CSR build =============================================
__global__ void count_deg_kernel(const int* __restrict__ dst)
{
    int e = blockIdx.x * 256 + threadIdx.x;
    if (e < EE) atomicAdd(&g_deg[dst[e]], 1);
}

__global__ void __launch_bounds__(1024) scan_deg_kernel()
{
    __shared__ int wsums[32];
    const int C = 49;
    int t = threadIdx.x;
    int lane = t & 31, wid = t >> 5;
    int begin = t * C;

    int s = 0;
    for (int i = 0; i < C; i++) {
        int idx = begin + i;
        if (idx < NN) s += g_deg[idx];
    }
    int incl = s;
    #pragma unroll
    for (int o = 1; o < 32; o <<= 1) {
        int v = __shfl_up_sync(0xffffffff, incl, o);
        if (lane >= o) incl += v;
    }
    if (lane == 31) wsums[wid] = incl;
    __syncthreads();
    if (wid == 0) {
        int w = wsums[lane];
        int wi = w;
        #pragma unroll
        for (int o = 1; o < 32; o <<= 1) {
            int v = __shfl_up_sync(0xffffffff, wi, o);
            if (lane >= o) wi += v;
        }
        wsums[lane] = wi - w;
    }
    __syncthreads();

    int run = wsums[wid] + incl - s;
    for (int i = 0; i < C; i++) {
        int idx = begin + i;
        if (idx < NN) {
            g_off[idx] = run;
            g_cur[idx] = run;
            run += g_deg[idx];
        }
    }
}

__global__ void scatter_edges_kernel(const int* __restrict__ src,
                                     const int* __restrict__ dst)
{
    int e = blockIdx.x * 256 + threadIdx.x;
    if (e < EE) {
        int p = atomicAdd(&g_cur[dst[e]], 1);
        g_pos[e] = p;
        g_srcs[p] = src[e];
    }
}

// ================= K5: edge MLP + attention logits (write sorted) =========
#define FEG 8
__global__ void __launch_bounds__(256) edge_att_kernel(
    const float* __restrict__ fe_g,
    const int* __restrict__ src, const int* __restrict__ dst,
    const float* __restrict__ we0, const float* __restrict__ we1)
{
    __shared__ __align__(16) float we0t[HA * FEG];
    __shared__ __align__(16) float we1s[HA * NH];

    int t = threadIdx.x;
    #pragma unroll
    for (int i = t; i < HA * FEG; i += 256) {
        int c = i >> 3, k = i & 7;
        we0t[i] = we0[k * HA + c];
        we1s[i] = we1[i];
    }
    __syncthreads();

    int e = blockIdx.x * 256 + t;
    if (e >= EE) return;

    float4 f0 = reinterpret_cast<const float4*>(fe_g)[e * 2];
    float4 f1 = reinterpret_cast<const float4*>(fe_g)[e * 2 + 1];

    float a[NH];
    #pragma unroll
    for (int h = 0; h < NH; h++) a[h] = 0.f;

    #pragma unroll 4
    for (int c = 0; c < HA; c++) {
        float4 wa = reinterpret_cast<const float4*>(we0t + c * 8)[0];
        float4 wb = reinterpret_cast<const float4*>(we0t + c * 8)[1];
        float hsum = f0.x*wa.x + f0.y*wa.y + f0.z*wa.z + f0.w*wa.w
                   + f1.x*wb.x + f1.y*wb.y + f1.z*wb.z + f1.w*wb.w;
        hsum = fmaxf(hsum, 0.f);
        float4 va = reinterpret_cast<const float4*>(we1s + c * 8)[0];
        float4 vb = reinterpret_cast<const float4*>(we1s + c * 8)[1];
        a[0] += hsum * va.x; a[1] += hsum * va.y;
        a[2] += hsum * va.z; a[3] += hsum * va.w;
        a[4] += hsum * vb.x; a[5] += hsum * vb.y;
        a[6] += hsum * vb.z; a[7] += hsum * vb.w;
    }

    int s = src[e], d = dst[e];
    float4 s0 = reinterpret_cast<const float4*>(g_a_src)[s * 2];
    float4 s1 = reinterpret_cast<const float4*>(g_a_src)[s * 2 + 1];
    float4 d0 = reinterpret_cast<const float4*>(g_a_dst)[d * 2];
    float4 d1 = reinterpret_cast<const float4*>(g_a_dst)[d * 2 + 1];

    float4 o0, o1;
    o0.x = fmaxf(a[0] + s0.x + d0.x, 0.f);
    o0.y = fmaxf(a[1] + s0.y + d0.y, 0.f);
    o0.z = fmaxf(a[2] + s0.z + d0.z, 0.f);
    o0.w = fmaxf(a[3] + s0.w + d0.w, 0.f);
    o1.x = fmaxf(a[4] + s1.x + d1.x, 0.f);
    o1.y = fmaxf(a[5] + s1.y + d1.y, 0.f);
    o1.z = fmaxf(a[6] + s1.z + d1.z, 0.f);
    o1.w = fmaxf(a[7] + s1.w + d1.w, 0.f);

    int p = g_pos[e];
    reinterpret_cast<float4*>(g_att)[p * 2]     = o0;
    reinterpret_cast<float4*>(g_att)[p * 2 + 1] = o1;
}

// ================= K6: single-pass softmax + aggregate + residual =========
__global__ void __launch_bounds__(256) softmax_agg_kernel(float* __restrict__ out)
{
    int warp = threadIdx.x >> 5;
    int l    = threadIdx.x & 31;
    int n = blockIdx.x * 8 + warp;
    if (n >= NN) return;

    int start = g_off[n];
    int cnt   = g_deg[n];
    if (l == 0) g_deg[n] = 0;     // reset for next replay
    int h     = l >> 2;

    float4 acc = make_float4(0.f, 0.f, 0.f, 0.f);
    float den = 0.f;
    for (int j = 0; j < cnt; j++) {
        int p = start + j;
        float ex = __expf(__ldg(&g_att[p * NH + h]));
        den += ex;
        int s = g_srcs[p];
        float4 v = reinterpret_cast<const float4*>(g_prop_src)[s * 32 + l];
        acc.x += ex * v.x;
        acc.y += ex * v.y;
        acc.z += ex * v.z;
        acc.w += ex * v.w;
    }

    float inv = 1.f / fmaxf(den, 1e-16f);
    float4 pd = reinterpret_cast<const float4*>(g_prop_dst)[n * 32 + l];
    float4 o;
    o.x = acc.x * inv + pd.x;
    o.y = acc.y * inv + pd.y;
    o.z = acc.z * inv + pd.z;
    o.w = acc.w * inv + pd.w;
    reinterpret_cast<float4*>(out)[n * 32 + l] = o;
}

// ================= launch ================================================
extern "C" void kernel_launch(void* const* d_in, const int* in_sizes, int n_in,
                              void* d_out, int out_size)
{
    const float* feat      = (const float*)d_in[0];
    const float* feat_edge = (const float*)d_in[1];
    const int*   src       = (const int*)  d_in[2];
    const int*   dst       = (const int*)  d_in[3];
    const float* was0      = (const float*)d_in[4];
    const float* was1      = (const float*)d_in[5];
    const float* wad0      = (const float*)d_in[6];
    const float* wad1      = (const float*)d_in[7];
    const float* we0       = (const float*)d_in[8];
    const float* we1       = (const float*)d_in[9];
    const float* wps       = (const float*)d_in[10];
    const float* bps       = (const float*)d_in[11];
    const float* wpd       = (const float*)d_in[12];
    const float* bpd       = (const float*)d_in[13];
    float* out = (float*)d_out;

    // prep: operand split (launch 0,1)
    split_feat_kernel<<<NN * 64 / 256, 256>>>(feat);
    split_w_kernel<<<6 * 64 * 64 / 256, 256>>>(wps, wpd, was0, wad0);

    // CSR histogram (launch 2)
    count_deg_kernel<<<(EE + 255) / 256, 256>>>(dst);

    // node GEMM at launch index 3 (ncu capture slot)
    node_gemm_kernel<<<dim3((NN + MT - 1) / MT, 6), 256>>>(bps, bpd);

    // CSR scan + scatter
    scan_deg_kernel<<<1, 1024>>>();
    scatter_edges_kernel<<<(EE + 255) / 256, 256>>>(src, dst);

    // attention layer 2
    att_layer2_kernel<<<NN / NB2, 128>>>(was1, wad1);

    // edge MLP + logits (written in CSR order)
    edge_att_kernel<<<(EE + 255) / 256, 256>>>(feat_edge, src, dst, we0, we1);

    // single-pass softmax + aggregation + residual (+ g_deg reset)
    softmax_agg_kernel<<<(NN + 7) / 8, 256>>>(out);
}

// round 14
// speedup vs baseline: 1.1474x; 1.0431x over previous
#include <cuda_runtime.h>
#include <cuda_bf16.h>
#include <cstdint>

#define NN 50000
#define EE 800000
#define FN 128
#define HA 64
#define NH 8

// ---------------- scratch ----------------
__device__ float g_prop_src[NN * FN];
__device__ float g_prop_dst[NN * FN];
__device__ float g_hs[NN * HA];
__device__ float g_hd[NN * HA];
__device__ float g_a_src[NN * NH];
__device__ float g_a_dst[NN * NH];
__device__ float g_att[EE * NH];     // dst-sorted order
__device__ int   g_deg[NN];          // zero at module load; re-zeroed by softmax_agg
__device__ int   g_off[NN];
__device__ int   g_cur[NN];
__device__ int   g_pos[EE];
__device__ int   g_srcs[EE];

// pre-split bf16 hi/lo pairs (u32 = bf16x2, low half = even k)
__device__ uint32_t g_Ah[NN * 64];     // feat  [node][kpair]   (16 uint4 per node)
__device__ uint32_t g_Al[NN * 64];
__device__ uint32_t g_Bh[6 * 64 * 64]; // [ypanel][kpair][col]  (64 cols per panel)
__device__ uint32_t g_Bl[6 * 64 * 64];

__device__ __forceinline__ void split_bf16x2(float x, float y,
                                             uint32_t& hi, uint32_t& lo) {
    __nv_bfloat16 hx = __float2bfloat16(x);
    __nv_bfloat16 hy = __float2bfloat16(y);
    float rx = x - __bfloat162float(hx);
    float ry = y - __bfloat162float(hy);
    __nv_bfloat16 lx = __float2bfloat16(rx);
    __nv_bfloat16 ly = __float2bfloat16(ry);
    hi = ((uint32_t)__bfloat16_as_ushort(hy) << 16) | __bfloat16_as_ushort(hx);
    lo = ((uint32_t)__bfloat16_as_ushort(ly) << 16) | __bfloat16_as_ushort(lx);
}

// ================= P1: split feat ========================================
__global__ void __launch_bounds__(256) split_feat_kernel(const float* __restrict__ feat)
{
    int idx = blockIdx.x * 256 + threadIdx.x;     // 0 .. NN*64-1
    float2 v = reinterpret_cast<const float2*>(feat)[idx];
    uint32_t h, l;
    split_bf16x2(v.x, v.y, h, l);
    g_Ah[idx] = h;
    g_Al[idx] = l;
}

// ================= P2: split weights -> panels ===========================
// panel y: 0,1 = wps cols [0:64),[64:128); 2,3 = wpd; 4 = was0; 5 = wad0
__global__ void __launch_bounds__(256) split_w_kernel(
    const float* __restrict__ wps, const float* __restrict__ wpd,
    const float* __restrict__ was0, const float* __restrict__ wad0)
{
    int idx = blockIdx.x * 256 + threadIdx.x;     // 0 .. 6*64*64-1
    int y  = idx >> 12;
    int kp = (idx >> 6) & 63;
    int c  = idx & 63;
    int k0 = kp * 2;
    float x, z;
    if (y < 2) {
        int col = (y & 1) * 64 + c;
        x = wps[k0 * FN + col]; z = wps[(k0 + 1) * FN + col];
    } else if (y < 4) {
        int col = (y & 1) * 64 + c;
        x = wpd[k0 * FN + col]; z = wpd[(k0 + 1) * FN + col];
    } else if (y == 4) {
        x = was0[k0 * HA + c]; z = was0[(k0 + 1) * HA + c];
    } else {
        x = wad0[k0 * HA + c]; z = wad0[(k0 + 1) * HA + c];
    }
    uint32_t h, l;
    split_bf16x2(x, z, h, l);
    g_Bh[idx] = h;
    g_Bl[idx] = l;
}

// ================= K1: node GEMM v3 ======================================
// block M128 x N64 (panel), full K=128 staged once; 8 warps = 4m x 2n,
// warp tile m32 x n32. products hi*hi + hi*lo + lo*hi.
// dynamic smem layout (u32 units):
//   sAh [0, 8704)        : 128 rows x 68 (64 kpairs + 4 pad)
//   sAl [8704, 17408)
//   sBh [17408, 22016)   : 64 kpairs x 72 (64 cols + 8 pad)
//   sBl [22016, 26624)
#define ARS 68   // A row stride u32 (17 uint4)
#define BRS 72   // B kpair stride u32 (18 uint4)
#define SMEM_U32 26624
#define SMEM_BYTES (SMEM_U32 * 4)

__device__ __forceinline__ void mma_bf16(float* c, const uint32_t* a,
                                         uint32_t b0, uint32_t b1) {
    asm volatile(
        "mma.sync.aligned.m16n8k16.row.col.f32.bf16.bf16.f32 "
        "{%0,%1,%2,%3}, {%4,%5,%6,%7}, {%8,%9}, {%0,%1,%2,%3};"
        : "+f"(c[0]), "+f"(c[1]), "+f"(c[2]), "+f"(c[3])
        : "r"(a[0]), "r"(a[1]), "r"(a[2]), "r"(a[3]), "r"(b0), "r"(b1));
}

__global__ void __launch_bounds__(256, 2) node_gemm_kernel(
    const float* __restrict__ bps, const float* __restrict__ bpd)
{
    extern __shared__ uint32_t sm[];
    uint32_t* sAh = sm;
    uint32_t* sAl = sm + 8704;
    uint32_t* sBh = sm + 17408;
    uint32_t* sBl = sm + 22016;

    const int tid = threadIdx.x;
    const int m0 = blockIdx.x * 128;
    const int yp = blockIdx.y;

    const int wid = tid >> 5;
    const int lane = tid & 31;
    const int warp_m = wid & 3;          // 0..3 -> m offset *32
    const int warp_n = wid >> 2;         // 0/1  -> n offset *32
    const int gid = lane >> 2;           // 0..7
    const int tig = lane & 3;            // 0..3
    const int m_w = warp_m * 32;
    const int n_w = warp_n * 32;

    // ---- stage A: 128 rows x 16 uint4 (hi+lo), 8 passes
    #pragma unroll
    for (int p = 0; p < 8; p++) {
        int idx = tid + p * 256;         // 0..2047
        int row = idx >> 4;
        int grp = idx & 15;
        int node = m0 + row;
        uint4 vh = make_uint4(0u, 0u, 0u, 0u);
        uint4 vl = make_uint4(0u, 0u, 0u, 0u);
        if (node < NN) {
            int gi = node * 16 + grp;
            vh = reinterpret_cast<const uint4*>(g_Ah)[gi];
            vl = reinterpret_cast<const uint4*>(g_Al)[gi];
        }
        reinterpret_cast<uint4*>(sAh)[row * 17 + grp] = vh;
        reinterpret_cast<uint4*>(sAl)[row * 17 + grp] = vl;
    }
    // ---- stage B: 64 kpairs x 16 uint4 (hi+lo), 4 passes
    #pragma unroll
    for (int p = 0; p < 4; p++) {
        int idx = tid + p * 256;         // 0..1023
        int kp = idx >> 4;
        int grp = idx & 15;
        int gi = yp * 1024 + kp * 16 + grp;
        uint4 vh = reinterpret_cast<const uint4*>(g_Bh)[gi];
        uint4 vl = reinterpret_cast<const uint4*>(g_Bl)[gi];
        reinterpret_cast<uint4*>(sBh)[kp * 18 + grp] = vh;
        reinterpret_cast<uint4*>(sBl)[kp * 18 + grp] = vl;
    }
    __syncthreads();

    float acc0[4][4], acc1[4][4];
    #pragma unroll
    for (int j = 0; j < 4; j++)
        #pragma unroll
        for (int i = 0; i < 4; i++) { acc0[j][i] = 0.f; acc1[j][i] = 0.f; }

    // ---- 8 k-steps of 16, no intermediate syncs
    #pragma unroll
    for (int ks = 0; ks < 8; ks++) {
        int a0 = (m_w + gid) * ARS + ks * 8 + tig;
        int a1 = a0 + 16 * ARS;
        uint32_t ah0[4], al0[4], ah1[4], al1[4];
        ah0[0] = sAh[a0];            al0[0] = sAl[a0];
        ah0[1] = sAh[a0 + 8 * ARS];  al0[1] = sAl[a0 + 8 * ARS];
        ah0[2] = sAh[a0 + 4];        al0[2] = sAl[a0 + 4];
        ah0[3] = sAh[a0 + 8 * ARS + 4]; al0[3] = sAl[a0 + 8 * ARS + 4];
        ah1[0] = sAh[a1];            al1[0] = sAl[a1];
        ah1[1] = sAh[a1 + 8 * ARS];  al1[1] = sAl[a1 + 8 * ARS];
        ah1[2] = sAh[a1 + 4];        al1[2] = sAl[a1 + 4];
        ah1[3] = sAh[a1 + 8 * ARS + 4]; al1[3] = sAl[a1 + 8 * ARS + 4];
        #pragma unroll
        for (int j = 0; j < 4; j++) {
            int col = n_w + j * 8 + gid;
            int b0i = (ks * 8 + tig) * BRS + col;
            int b1i = b0i + 4 * BRS;
            uint32_t bh0 = sBh[b0i], bh1 = sBh[b1i];
            uint32_t bl0 = sBl[b0i], bl1 = sBl[b1i];
            mma_bf16(acc0[j], ah0, bh0, bh1);
            mma_bf16(acc0[j], ah0, bl0, bl1);
            mma_bf16(acc0[j], al0, bh0, bh1);
            mma_bf16(acc1[j], ah1, bh0, bh1);
            mma_bf16(acc1[j], ah1, bl0, bl1);
            mma_bf16(acc1[j], al1, bh0, bh1);
        }
    }

    // ---- epilogue
    #pragma unroll
    for (int t = 0; t < 2; t++) {
        float (*acc)[4] = (t == 0) ? acc0 : acc1;
        #pragma unroll
        for (int half = 0; half < 2; half++) {
            int node = m0 + m_w + t * 16 + gid + half * 8;
            if (node >= NN) continue;
            #pragma unroll
            for (int j = 0; j < 4; j++) {
                int cl = n_w + j * 8 + tig * 2;   // 0..63 within panel
                float v0 = acc[j][half * 2 + 0];
                float v1 = acc[j][half * 2 + 1];
                if (yp < 2) {
                    int col = (yp & 1) * 64 + cl;
                    g_prop_src[node * FN + col]     = v0 + bps[col];
                    g_prop_src[node * FN + col + 1] = v1 + bps[col + 1];
                } else if (yp < 4) {
                    int col = (yp & 1) * 64 + cl;
                    g_prop_dst[node * FN + col]     = v0 + bpd[col];
                    g_prop_dst[node * FN + col + 1] = v1 + bpd[col + 1];
                } else if (yp == 4) {
                    g_hs[node * HA + cl]     = fmaxf(v0, 0.f);
                    g_hs[node * HA + cl + 1] = fmaxf(v1, 0.f);
                } else {
                    g_hd[node * HA + cl]     = fmaxf(v0, 0.f);
                    g_hd[node * HA + cl + 1] = fmaxf(v1, 0.f);
                }
            }
        }
    }
}

// ================= K2: attention second layer ============================
#define NB2 8
__global__ void __launch_bounds__(128) att_layer2_kernel(
    const float* __restrict__ was1, const float* __restrict__ wad1)
{
    __shared__ __align__(16) float hs[NB2][HA];
    __shared__ __align__(16) float hd[NB2][HA];
    int t = threadIdx.x;
    int n0 = blockIdx.x * NB2;

    #pragma unroll
    for (int p = 0; p < 4; p++) {
        int idx = t + p * 128;
        int j = idx >> 6, c = idx & 63;
        hs[j][c] = g_hs[(n0 + j) * HA + c];
        hd[j][c] = g_hd[(n0 + j) * HA + c];
    }
    __syncthreads();

    int j = t >> 4, r = t & 15;
    if (r < NH) {
        float a = 0.f;
        #pragma unroll 8
        for (int k = 0; k < HA; k++) a += hs[j][k] * was1[k * NH + r];
        g_a_src[(n0 + j) * NH + r] = a;
    } else {
        int h = r - NH;
        float a = 0.f;
        #pragma unroll 8
        for (int k = 0; k < HA; k++) a += hd[j][k] * wad1[k * NH + h];
        g_a_dst[(n0 + j) * NH + h] = a;
    }
}

// ================= CSR build =============================================
__global__ void count_deg_kernel(const int* __restrict__ dst)
{
    int e = blockIdx.x * 256 + threadIdx.x;
    if (e < EE) atomicAdd(&g_deg[dst[e]], 1);
}

__global__ void __launch_bounds__(1024) scan_deg_kernel()
{
    __shared__ int wsums[32];
    const int C = 49;
    int t = threadIdx.x;
    int lane = t & 31, wid = t >> 5;
    int begin = t * C;

    int s = 0;
    for (int i = 0; i < C; i++) {
        int idx = begin + i;
        if (idx < NN) s += g_deg[idx];
    }
    int incl = s;
    #pragma unroll
    for (int o = 1; o < 32; o <<= 1) {
        int v = __shfl_up_sync(0xffffffff, incl, o);
        if (lane >= o) incl += v;
    }
    if (lane == 31) wsums[wid] = incl;
    __syncthreads();
    if (wid == 0) {
        int w = wsums[lane];
        int wi = w;
        #pragma unroll
        for (int o = 1; o < 32; o <<= 1) {
            int v = __shfl_up_sync(0xffffffff, wi, o);
            if (lane >= o) wi += v;
        }
        wsums[lane] = wi - w;
    }
    __syncthreads();

    int run = wsums[wid] + incl - s;
    for (int i = 0; i < C; i++) {
        int idx = begin + i;
        if (idx < NN) {
            g_off[idx] = run;
            g_cur[idx] = run;
            run += g_deg[idx];
        }
    }
}

__global__ void scatter_edges_kernel(const int* __restrict__ src,
                                     const int* __restrict__ dst)
{
    int e = blockIdx.x * 256 + threadIdx.x;
    if (e < EE) {
        int p = atomicAdd(&g_cur[dst[e]], 1);
        g_pos[e] = p;
        g_srcs[p] = src[e];
    }
}

// ================= K5: edge MLP + attention logits (write sorted) =========
#define FEG 8
__global__ void __launch_bounds__(256) edge_att_kernel(
    const float* __restrict__ fe_g,
    const int* __restrict__ src, const int* __restrict__ dst,
    const float* __restrict__ we0, const float* __restrict__ we1)
{
    __shared__ __align__(16) float we0t[HA * FEG];
    __shared__ __align__(16) float we1s[HA * NH];

    int t = threadIdx.x;
    #pragma unroll
    for (int i = t; i < HA * FEG; i += 256) {
        int c = i >> 3, k = i & 7;
        we0t[i] = we0[k * HA + c];
        we1s[i] = we1[i];
    }
    __syncthreads();

    int e = blockIdx.x * 256 + t;
    if (e >= EE) return;

    float4 f0 = reinterpret_cast<const float4*>(fe_g)[e * 2];
    float4 f1 = reinterpret_cast<const float4*>(fe_g)[e * 2 + 1];

    float a[NH];
    #pragma unroll
    for (int h = 0; h < NH; h++) a[h] = 0.f;

    #pragma unroll 4
    for (int c = 0; c < HA; c++) {
        float4 wa = reinterpret_cast<const float4*>(we0t + c * 8)[0];
        float4 wb = reinterpret_cast<const float4*>(we0t + c * 8)[1];
        float hsum = f0.x*wa.x + f0.y*wa.y + f0.z*wa.z + f0.w*wa.w
                   + f1.x*wb.x + f1.y*wb.y + f1.z*wb.z + f1.w*wb.w;
        hsum = fmaxf(hsum, 0.f);
        float4 va = reinterpret_cast<const float4*>(we1s + c * 8)[0];
        float4 vb = reinterpret_cast<const float4*>(we1s + c * 8)[1];
        a[0] += hsum * va.x; a[1] += hsum * va.y;
        a[2] += hsum * va.z; a[3] += hsum * va.w;
        a[4] += hsum * vb.x; a[5] += hsum * vb.y;
        a[6] += hsum * vb.z; a[7] += hsum * vb.w;
    }

    int s = src[e], d = dst[e];
    float4 s0 = reinterpret_cast<const float4*>(g_a_src)[s * 2];
    float4 s1 = reinterpret_cast<const float4*>(g_a_src)[s * 2 + 1];
    float4 d0 = reinterpret_cast<const float4*>(g_a_dst)[d * 2];
    float4 d1 = reinterpret_cast<const float4*>(g_a_dst)[d * 2 + 1];

    float4 o0, o1;
    o0.x = fmaxf(a[0] + s0.x + d0.x, 0.f);
    o0.y = fmaxf(a[1] + s0.y + d0.y, 0.f);
    o0.z = fmaxf(a[2] + s0.z + d0.z, 0.f);
    o0.w = fmaxf(a[3] + s0.w + d0.w, 0.f);
    o1.x = fmaxf(a[4] + s1.x + d1.x, 0.f);
    o1.y = fmaxf(a[5] + s1.y + d1.y, 0.f);
    o1.z = fmaxf(a[6] + s1.z + d1.z, 0.f);
    o1.w = fmaxf(a[7] + s1.w + d1.w, 0.f);

    int p = g_pos[e];
    reinterpret_cast<float4*>(g_att)[p * 2]     = o0;
    reinterpret_cast<float4*>(g_att)[p * 2 + 1] = o1;
}

// ================= K6: single-pass softmax + aggregate + residual =========
__global__ void __launch_bounds__(256) softmax_agg_kernel(float* __restrict__ out)
{
    int warp = threadIdx.x >> 5;
    int l    = threadIdx.x & 31;
    int n = blockIdx.x * 8 + warp;
    if (n >= NN) return;

    int start = g_off[n];
    int cnt   = g_deg[n];
    if (l == 0) g_deg[n] = 0;     // reset for next replay
    int h     = l >> 2;

    float4 acc = make_float4(0.f, 0.f, 0.f, 0.f);
    float den = 0.f;
    for (int j = 0; j < cnt; j++) {
        int p = start + j;
        float ex = __expf(__ldg(&g_att[p * NH + h]));
        den += ex;
        int s = g_srcs[p];
        float4 v = reinterpret_cast<const float4*>(g_prop_src)[s * 32 + l];
        acc.x += ex * v.x;
        acc.y += ex * v.y;
        acc.z += ex * v.z;
        acc.w += ex * v.w;
    }

    float inv = 1.f / fmaxf(den, 1e-16f);
    float4 pd = reinterpret_cast<const float4*>(g_prop_dst)[n * 32 + l];
    float4 o;
    o.x = acc.x * inv + pd.x;
    o.y = acc.y * inv + pd.y;
    o.z = acc.z * inv + pd.z;
    o.w = acc.w * inv + pd.w;
    reinterpret_cast<float4*>(out)[n * 32 + l] = o;
}

// ================= launch ================================================
extern "C" void kernel_launch(void* const* d_in, const int* in_sizes, int n_in,
                              void* d_out, int out_size)
{
    const float* feat      = (const float*)d_in[0];
    const float* feat_edge = (const float*)d_in[1];
    const int*   src       = (const int*)  d_in[2];
    const int*   dst       = (const int*)  d_in[3];
    const float* was0      = (const float*)d_in[4];
    const float* was1      = (const float*)d_in[5];
    const float* wad0      = (const float*)d_in[6];
    const float* wad1      = (const float*)d_in[7];
    const float* we0       = (const float*)d_in[8];
    const float* we1       = (const float*)d_in[9];
    const float* wps       = (const float*)d_in[10];
    const float* bps       = (const float*)d_in[11];
    const float* wpd       = (const float*)d_in[12];
    const float* bpd       = (const float*)d_in[13];
    float* out = (float*)d_out;

    // non-stream API, capture-safe, called unconditionally
    cudaFuncSetAttribute(node_gemm_kernel,
                         cudaFuncAttributeMaxDynamicSharedMemorySize,
                         SMEM_BYTES);

    // prep: operand split (launch 0,1)
    split_feat_kernel<<<NN * 64 / 256, 256>>>(feat);
    split_w_kernel<<<6 * 64 * 64 / 256, 256>>>(wps, wpd, was0, wad0);

    // CSR histogram (launch 2)
    count_deg_kernel<<<(EE + 255) / 256, 256>>>(dst);

    // node GEMM at launch index 3 (ncu capture slot)
    node_gemm_kernel<<<dim3((NN + 127) / 128, 6), 256, SMEM_BYTES>>>(bps, bpd);

    // CSR scan + scatter
    scan_deg_kernel<<<1, 1024>>>();
    scatter_edges_kernel<<<(EE + 255) / 256, 256>>>(src, dst);

    // attention layer 2
    att_layer2_kernel<<<NN / NB2, 128>>>(was1, wad1);

    // edge MLP + logits (written in CSR order)
    edge_att_kernel<<<(EE + 255) / 256, 256>>>(feat_edge, src, dst, we0, we1);

    // single-pass softmax + aggregation + residual (+ g_deg reset)
    softmax_agg_kernel<<<(NN + 7) / 8, 256>>>(out);
}

// round 16
// speedup vs baseline: 1.1633x; 1.0139x over previous
#include <cuda_runtime.h>
#include <cuda_bf16.h>
#include <cstdint>

#define NN 50000
#define EE 800000
#define FN 128
#define HA 64
#define NH 8

// ---------------- scratch ----------------
__device__ float g_prop_src[NN * FN];
__device__ float g_prop_dst[NN * FN];
__device__ float g_hs[NN * HA];
__device__ float g_hd[NN * HA];
__device__ float g_a_src[NN * NH];
__device__ float g_a_dst[NN * NH];
__device__ float g_att[EE * NH];     // dst-sorted order
__device__ int   g_deg[NN];          // zero at module load; re-zeroed by softmax_agg
__device__ int   g_off[NN];
__device__ int   g_cur[NN];
__device__ int   g_pos[EE];
__device__ int   g_srcs[EE];

// pre-split bf16 hi/lo pairs (u32 = bf16x2, low half = even k)
__device__ uint32_t g_Ah[NN * 64];     // feat  [node][kpair]   (16 uint4 per node)
__device__ uint32_t g_Al[NN * 64];
__device__ uint32_t g_Bh[6 * 64 * 64]; // [ypanel][kpair][col]
__device__ uint32_t g_Bl[6 * 64 * 64];

__device__ __forceinline__ void split_bf16x2(float x, float y,
                                             uint32_t& hi, uint32_t& lo) {
    __nv_bfloat16 hx = __float2bfloat16(x);
    __nv_bfloat16 hy = __float2bfloat16(y);
    float rx = x - __bfloat162float(hx);
    float ry = y - __bfloat162float(hy);
    __nv_bfloat16 lx = __float2bfloat16(rx);
    __nv_bfloat16 ly = __float2bfloat16(ry);
    hi = ((uint32_t)__bfloat16_as_ushort(hy) << 16) | __bfloat16_as_ushort(hx);
    lo = ((uint32_t)__bfloat16_as_ushort(ly) << 16) | __bfloat16_as_ushort(lx);
}

// ================= P1: split feat ========================================
__global__ void __launch_bounds__(256) split_feat_kernel(const float* __restrict__ feat)
{
    int idx = blockIdx.x * 256 + threadIdx.x;     // 0 .. NN*64-1
    float2 v = reinterpret_cast<const float2*>(feat)[idx];
    uint32_t h, l;
    split_bf16x2(v.x, v.y, h, l);
    g_Ah[idx] = h;
    g_Al[idx] = l;
}

// ================= P2: split weights -> panels ===========================
// panel y: 0,1 = wps cols [0:64),[64:128); 2,3 = wpd; 4 = was0; 5 = wad0
__global__ void __launch_bounds__(256) split_w_kernel(
    const float* __restrict__ wps, const float* __restrict__ wpd,
    const float* __restrict__ was0, const float* __restrict__ wad0)
{
    int idx = blockIdx.x * 256 + threadIdx.x;     // 0 .. 6*64*64-1
    int y  = idx >> 12;
    int kp = (idx >> 6) & 63;
    int c  = idx & 63;
    int k0 = kp * 2;
    float x, z;
    if (y < 2) {
        int col = (y & 1) * 64 + c;
        x = wps[k0 * FN + col]; z = wps[(k0 + 1) * FN + col];
    } else if (y < 4) {
        int col = (y & 1) * 64 + c;
        x = wpd[k0 * FN + col]; z = wpd[(k0 + 1) * FN + col];
    } else if (y == 4) {
        x = was0[k0 * HA + c]; z = was0[(k0 + 1) * HA + c];
    } else {
        x = wad0[k0 * HA + c]; z = wad0[(k0 + 1) * HA + c];
    }
    uint32_t h, l;
    split_bf16x2(x, z, h, l);
    g_Bh[idx] = h;
    g_Bl[idx] = l;
}

// ================= K1: node GEMM v4 ======================================
// block M128 x N64 (panel); K staged in 2 chunks of 64 (32 kpairs).
// 8 warps = 4m x 2n, warp tile m32 x n32; hi*hi + hi*lo + lo*hi.
// smem (u32): sAh 128x36, sAl 128x36, sBh 32x72, sBl 32x72 = 13824 u32 = 55.3 KB
#define ARS 36   // A row stride u32 (9 uint4)
#define BRS 72   // B kpair stride u32 (18 uint4)
#define SMEM_U32 (2 * 128 * ARS + 2 * 32 * BRS)
#define SMEM_BYTES (SMEM_U32 * 4)

__device__ __forceinline__ void mma_bf16(float* c, const uint32_t* a,
                                         uint32_t b0, uint32_t b1) {
    asm volatile(
        "mma.sync.aligned.m16n8k16.row.col.f32.bf16.bf16.f32 "
        "{%0,%1,%2,%3}, {%4,%5,%6,%7}, {%8,%9}, {%0,%1,%2,%3};"
        : "+f"(c[0]), "+f"(c[1]), "+f"(c[2]), "+f"(c[3])
        : "r"(a[0]), "r"(a[1]), "r"(a[2]), "r"(a[3]), "r"(b0), "r"(b1));
}

__global__ void __launch_bounds__(256, 3) node_gemm_kernel(
    const float* __restrict__ bps, const float* __restrict__ bpd)
{
    extern __shared__ uint32_t sm[];
    uint32_t* sAh = sm;                       // 4608
    uint32_t* sAl = sm + 128 * ARS;           // 4608
    uint32_t* sBh = sm + 2 * 128 * ARS;       // 2304
    uint32_t* sBl = sBh + 32 * BRS;

    const int tid = threadIdx.x;
    const int m0 = blockIdx.x * 128;
    const int yp = blockIdx.y;

    const int wid = tid >> 5;
    const int lane = tid & 31;
    const int warp_m = wid & 3;
    const int warp_n = wid >> 2;
    const int gid = lane >> 2;
    const int tig = lane & 3;
    const int m_w = warp_m * 32;
    const int n_w = warp_n * 32;

    float acc0[4][4], acc1[4][4];
    #pragma unroll
    for (int j = 0; j < 4; j++)
        #pragma unroll
        for (int i = 0; i < 4; i++) { acc0[j][i] = 0.f; acc1[j][i] = 0.f; }

    #pragma unroll
    for (int ck = 0; ck < 2; ck++) {
        if (ck) __syncthreads();             // protect previous chunk reads

        // ---- stage A: 128 rows x 8 uint4 (this chunk), hi+lo; 4 passes
        #pragma unroll
        for (int p = 0; p < 4; p++) {
            int idx = tid + p * 256;         // 0..1023
            int row = idx >> 3;
            int grp = idx & 7;
            int node = m0 + row;
            uint4 vh = make_uint4(0u, 0u, 0u, 0u);
            uint4 vl = make_uint4(0u, 0u, 0u, 0u);
            if (node < NN) {
                int gi = node * 16 + ck * 8 + grp;
                vh = reinterpret_cast<const uint4*>(g_Ah)[gi];
                vl = reinterpret_cast<const uint4*>(g_Al)[gi];
            }
            reinterpret_cast<uint4*>(sAh)[row * 9 + grp] = vh;
            reinterpret_cast<uint4*>(sAl)[row * 9 + grp] = vl;
        }
        // ---- stage B: 32 kpairs x 16 uint4, hi+lo; 2 passes
        #pragma unroll
        for (int p = 0; p < 2; p++) {
            int idx = tid + p * 256;         // 0..511
            int kp = idx >> 4;
            int grp = idx & 15;
            int gi = yp * 1024 + (ck * 32 + kp) * 16 + grp;
            uint4 vh = reinterpret_cast<const uint4*>(g_Bh)[gi];
            uint4 vl = reinterpret_cast<const uint4*>(g_Bl)[gi];
            reinterpret_cast<uint4*>(sBh)[kp * 18 + grp] = vh;
            reinterpret_cast<uint4*>(sBl)[kp * 18 + grp] = vl;
        }
        __syncthreads();

        // ---- 4 k-steps of 16 in this chunk
        #pragma unroll
        for (int ks = 0; ks < 4; ks++) {
            int a0 = (m_w + gid) * ARS + ks * 8 + tig;
            int a1 = a0 + 16 * ARS;
            uint32_t ah0[4], al0[4], ah1[4], al1[4];
            ah0[0] = sAh[a0];               al0[0] = sAl[a0];
            ah0[1] = sAh[a0 + 8 * ARS];     al0[1] = sAl[a0 + 8 * ARS];
            ah0[2] = sAh[a0 + 4];           al0[2] = sAl[a0 + 4];
            ah0[3] = sAh[a0 + 8 * ARS + 4]; al0[3] = sAl[a0 + 8 * ARS + 4];
            ah1[0] = sAh[a1];               al1[0] = sAl[a1];
            ah1[1] = sAh[a1 + 8 * ARS];     al1[1] = sAl[a1 + 8 * ARS];
            ah1[2] = sAh[a1 + 4];           al1[2] = sAl[a1 + 4];
            ah1[3] = sAh[a1 + 8 * ARS + 4]; al1[3] = sAl[a1 + 8 * ARS + 4];
            #pragma unroll
            for (int j = 0; j < 4; j++) {
                int col = n_w + j * 8 + gid;
                int b0i = (ks * 8 + tig) * BRS + col;
                int b1i = b0i + 4 * BRS;
                uint32_t bh0 = sBh[b0i], bh1 = sBh[b1i];
                uint32_t bl0 = sBl[b0i], bl1 = sBl[b1i];
                mma_bf16(acc0[j], ah0, bh0, bh1);
                mma_bf16(acc0[j], ah0, bl0, bl1);
                mma_bf16(acc0[j], al0, bh0, bh1);
                mma_bf16(acc1[j], ah1, bh0, bh1);
                mma_bf16(acc1[j], ah1, bl0, bl1);
                mma_bf16(acc1[j], al1, bh0, bh1);
            }
        }
    }

    // ---- epilogue
    #pragma unroll
    for (int t = 0; t < 2; t++) {
        float (*acc)[4] = (t == 0) ? acc0 : acc1;
        #pragma unroll
        for (int half = 0; half < 2; half++) {
            int node = m0 + m_w + t * 16 + gid + half * 8;
            if (node >= NN) continue;
            #pragma unroll
            for (int j = 0; j < 4; j++) {
                int cl = n_w + j * 8 + tig * 2;
                float v0 = acc[j][half * 2 + 0];
                float v1 = acc[j][half * 2 + 1];
                if (yp < 2) {
                    int col = (yp & 1) * 64 + cl;
                    g_prop_src[node * FN + col]     = v0 + bps[col];
                    g_prop_src[node * FN + col + 1] = v1 + bps[col + 1];
                } else if (yp < 4) {
                    int col = (yp & 1) * 64 + cl;
                    g_prop_dst[node * FN + col]     = v0 + bpd[col];
                    g_prop_dst[node * FN + col + 1] = v1 + bpd[col + 1];
                } else if (yp == 4) {
                    g_hs[node * HA + cl]     = fmaxf(v0, 0.f);
                    g_hs[node * HA + cl + 1] = fmaxf(v1, 0.f);
                } else {
                    g_hd[node * HA + cl]     = fmaxf(v0, 0.f);
                    g_hd[node * HA + cl + 1] = fmaxf(v1, 0.f);
                }
            }
        }
    }
}

// ================= K2: attention second layer ============================
#define NB2 8
__global__ void __launch_bounds__(128) att_layer2_kernel(
    const float* __restrict__ was1, const float* __restrict__ wad1)
{
    __shared__ __align__(16) float hs[NB2][HA];
    __shared__ __align__(16) float hd[NB2][HA];
    int t = threadIdx.x;
    int n0 = blockIdx.x * NB2;

    #pragma unroll
    for (int p = 0; p < 4; p++) {
        int idx = t + p * 128;
        int j = idx >> 6, c = idx & 63;
        hs[j][c] = g_hs[(n0 + j) * HA + c];
        hd[j][c] = g_hd[(n0 + j) * HA + c];
    }
    __syncthreads();

    int j = t >> 4, r = t & 15;
    if (r < NH) {
        float a = 0.f;
        #pragma unroll 8
        for (int k = 0; k < HA; k++) a += hs[j][k] * was1[k * NH + r];
        g_a_src[(n0 + j) * NH + r] = a;
    } else {
        int h = r - NH;
        float a = 0.f;
        #pragma unroll 8
        for (int k = 0; k < HA; k++) a += hd[j][k] * wad1[k * NH + h];
        g_a_dst[(n0 + j) * NH + h] = a;
    }
}

// ================= CSR build =============================================
__global__ void count_deg_kernel(const int* __restrict__ dst)
{
    int e = blockIdx.x * 256 + threadIdx.x;
    if (e < EE) atomicAdd(&g_deg[dst[e]], 1);
}

__global__ void __launch_bounds__(1024) scan_deg_kernel()
{
    __shared__ int wsums[32];
    const int C = 49;
    int t = threadIdx.x;
    int lane = t & 31, wid = t >> 5;
    int begin = t * C;

    int s = 0;
    for (int i = 0; i < C; i++) {
        int idx = begin + i;
        if (idx < NN) s += g_deg[idx];
    }
    int incl = s;
    #pragma unroll
    for (int o = 1; o < 32; o <<= 1) {
        int v = __shfl_up_sync(0xffffffff, incl, o);
        if (lane >= o) incl += v;
    }
    if (lane == 31) wsums[wid] = incl;
    __syncthreads();
    if (wid == 0) {
        int w = wsums[lane];
        int wi = w;
        #pragma unroll
        for (int o = 1; o < 32; o <<= 1) {
            int v = __shfl_up_sync(0xffffffff, wi, o);
            if (lane >= o) wi += v;
        }
        wsums[lane] = wi - w;
    }
    __syncthreads();

    int run = wsums[wid] + incl - s;
    for (int i = 0; i < C; i++) {
        int idx = begin + i;
        if (idx < NN) {
            g_off[idx] = run;
            g_cur[idx] = run;
            run += g_deg[idx];
        }
    }
}

__global__ void scatter_edges_kernel(const int* __restrict__ src,
                                     const int* __restrict__ dst)
{
    int e = blockIdx.x * 256 + threadIdx.x;
    if (e < EE) {
        int p = atomicAdd(&g_cur[dst[e]], 1);
        g_pos[e] = p;
        g_srcs[p] = src[e];
    }
}

// ================= K5: edge MLP + attention logits (write sorted) =========
#define FEG 8
__global__ void __launch_bounds__(256) edge_att_kernel(
    const float* __restrict__ fe_g,
    const int* __restrict__ src, const int* __restrict__ dst,
    const float* __restrict__ we0, const float* __restrict__ we1)
{
    __shared__ __align__(16) float we0t[HA * FEG];
    __shared__ __align__(16) float we1s[HA * NH];

    int t = threadIdx.x;
    #pragma unroll
    for (int i = t; i < HA * FEG; i += 256) {
        int c = i >> 3, k = i & 7;
        we0t[i] = we0[k * HA + c];
        we1s[i] = we1[i];
    }
    __syncthreads();

    int e = blockIdx.x * 256 + t;
    if (e >= EE) return;

    float4 f0 = reinterpret_cast<const float4*>(fe_g)[e * 2];
    float4 f1 = reinterpret_cast<const float4*>(fe_g)[e * 2 + 1];

    float a[NH];
    #pragma unroll
    for (int h = 0; h < NH; h++) a[h] = 0.f;

    #pragma unroll 4
    for (int c = 0; c < HA; c++) {
        float4 wa = reinterpret_cast<const float4*>(we0t + c * 8)[0];
        float4 wb = reinterpret_cast<const float4*>(we0t + c * 8)[1];
        float hsum = f0.x*wa.x + f0.y*wa.y + f0.z*wa.z + f0.w*wa.w
                   + f1.x*wb.x + f1.y*wb.y + f1.z*wb.z + f1.w*wb.w;
        hsum = fmaxf(hsum, 0.f);
        float4 va = reinterpret_cast<const float4*>(we1s + c * 8)[0];
        float4 vb = reinterpret_cast<const float4*>(we1s + c * 8)[1];
        a[0] += hsum * va.x; a[1] += hsum * va.y;
        a[2] += hsum * va.z; a[3] += hsum * va.w;
        a[4] += hsum * vb.x; a[5] += hsum * vb.y;
        a[6] += hsum * vb.z; a[7] += hsum * vb.w;
    }

    int s = src[e], d = dst[e];
    float4 s0 = reinterpret_cast<const float4*>(g_a_src)[s * 2];
    float4 s1 = reinterpret_cast<const float4*>(g_a_src)[s * 2 + 1];
    float4 d0 = reinterpret_cast<const float4*>(g_a_dst)[d * 2];
    float4 d1 = reinterpret_cast<const float4*>(g_a_dst)[d * 2 + 1];

    float4 o0, o1;
    o0.x = fmaxf(a[0] + s0.x + d0.x, 0.f);
    o0.y = fmaxf(a[1] + s0.y + d0.y, 0.f);
    o0.z = fmaxf(a[2] + s0.z + d0.z, 0.f);
    o0.w = fmaxf(a[3] + s0.w + d0.w, 0.f);
    o1.x = fmaxf(a[4] + s1.x + d1.x, 0.f);
    o1.y = fmaxf(a[5] + s1.y + d1.y, 0.f);
    o1.z = fmaxf(a[6] + s1.z + d1.z, 0.f);
    o1.w = fmaxf(a[7] + s1.w + d1.w, 0.f);

    int p = g_pos[e];
    reinterpret_cast<float4*>(g_att)[p * 2]     = o0;
    reinterpret_cast<float4*>(g_att)[p * 2 + 1] = o1;
}

// ================= K6: softmax + aggregate + residual (4x unrolled) ======
__global__ void __launch_bounds__(256) softmax_agg_kernel(float* __restrict__ out)
{
    int warp = threadIdx.x >> 5;
    int l    = threadIdx.x & 31;
    int n = blockIdx.x * 8 + warp;
    if (n >= NN) return;

    int start = g_off[n];
    int cnt   = g_deg[n];
    if (l == 0) g_deg[n] = 0;     // reset for next replay
    int h     = l >> 2;

    float4 acc = make_float4(0.f, 0.f, 0.f, 0.f);
    float den = 0.f;

    int j = 0;
    for (; j + 4 <= cnt; j += 4) {
        int p = start + j;
        // front-load all independent loads (raise MLP)
        float a0 = __ldg(&g_att[(p + 0) * NH + h]);
        float a1 = __ldg(&g_att[(p + 1) * NH + h]);
        float a2 = __ldg(&g_att[(p + 2) * NH + h]);
        float a3 = __ldg(&g_att[(p + 3) * NH + h]);
        int s0 = __ldg(&g_srcs[p + 0]);
        int s1 = __ldg(&g_srcs[p + 1]);
        int s2 = __ldg(&g_srcs[p + 2]);
        int s3 = __ldg(&g_srcs[p + 3]);
        float4 v0 = reinterpret_cast<const float4*>(g_prop_src)[s0 * 32 + l];
        float4 v1 = reinterpret_cast<const float4*>(g_prop_src)[s1 * 32 + l];
        float4 v2 = reinterpret_cast<const float4*>(g_prop_src)[s2 * 32 + l];
        float4 v3 = reinterpret_cast<const float4*>(g_prop_src)[s3 * 32 + l];
        float e0 = __expf(a0), e1 = __expf(a1), e2 = __expf(a2), e3 = __expf(a3);
        den += (e0 + e1) + (e2 + e3);
        acc.x += e0 * v0.x + e1 * v1.x + e2 * v2.x + e3 * v3.x;
        acc.y += e0 * v0.y + e1 * v1.y + e2 * v2.y + e3 * v3.y;
        acc.z += e0 * v0.z + e1 * v1.z + e2 * v2.z + e3 * v3.z;
        acc.w += e0 * v0.w + e1 * v1.w + e2 * v2.w + e3 * v3.w;
    }
    for (; j < cnt; j++) {
        int p = start + j;
        float ex = __expf(__ldg(&g_att[p * NH + h]));
        den += ex;
        int s = __ldg(&g_srcs[p]);
        float4 v = reinterpret_cast<const float4*>(g_prop_src)[s * 32 + l];
        acc.x += ex * v.x;
        acc.y += ex * v.y;
        acc.z += ex * v.z;
        acc.w += ex * v.w;
    }

    float inv = 1.f / fmaxf(den, 1e-16f);
    float4 pd = reinterpret_cast<const float4*>(g_prop_dst)[n * 32 + l];
    float4 o;
    o.x = acc.x * inv + pd.x;
    o.y = acc.y * inv + pd.y;
    o.z = acc.z * inv + pd.z;
    o.w = acc.w * inv + pd.w;
    reinterpret_cast<float4*>(out)[n * 32 + l] = o;
}

// ================= launch ================================================
extern "C" void kernel_launch(void* const* d_in, const int* in_sizes, int n_in,
                              void* d_out, int out_size)
{
    const float* feat      = (const float*)d_in[0];
    const float* feat_edge = (const float*)d_in[1];
    const int*   src       = (const int*)  d_in[2];
    const int*   dst       = (const int*)  d_in[3];
    const float* was0      = (const float*)d_in[4];
    const float* was1      = (const float*)d_in[5];
    const float* wad0      = (const float*)d_in[6];
    const float* wad1      = (const float*)d_in[7];
    const float* we0       = (const float*)d_in[8];
    const float* we1       = (const float*)d_in[9];
    const float* wps       = (const float*)d_in[10];
    const float* bps       = (const float*)d_in[11];
    const float* wpd       = (const float*)d_in[12];
    const float* bpd       = (const float*)d_in[13];
    float* out = (float*)d_out;

    // non-stream API, capture-safe, called unconditionally
    cudaFuncSetAttribute(node_gemm_kernel,
                         cudaFuncAttributeMaxDynamicSharedMemorySize,
                         SMEM_BYTES);

    // prep: operand split
    split_feat_kernel<<<NN * 64 / 256, 256>>>(feat);
    split_w_kernel<<<6 * 64 * 64 / 256, 256>>>(wps, wpd, was0, wad0);

    // CSR histogram
    count_deg_kernel<<<(EE + 255) / 256, 256>>>(dst);

    // node GEMM (ncu capture slot)
    node_gemm_kernel<<<dim3((NN + 127) / 128, 6), 256, SMEM_BYTES>>>(bps, bpd);

    // CSR scan + scatter
    scan_deg_kernel<<<1, 1024>>>();
    scatter_edges_kernel<<<(EE + 255) / 256, 256>>>(src, dst);

    // attention layer 2
    att_layer2_kernel<<<NN / NB2, 128>>>(was1, wad1);

    // edge MLP + logits (written in CSR order)
    edge_att_kernel<<<(EE + 255) / 256, 256>>>(feat_edge, src, dst, we0, we1);

    // softmax + aggregation + residual (+ g_deg reset)
    softmax_agg_kernel<<<(NN + 7) / 8, 256>>>(out);
}